// round 1
// baseline (speedup 1.0000x reference)
#include <cuda_runtime.h>
#include <cstdint>

// KA_BSpline_Core: out[n] = b_out + sum_q a[q] * spline_q( sigmoid(2*scale*(emb[n]·W[q]+b_inner[q])) )
//
// Strategy: thread-per-point. emb rows staged through shared memory with
// cp.async (double-buffered K-chunks of 32) for coalesced HBM reads.
// GEMV accumulation uses packed fma.rn.f32x2 (K-dimension packed in pairs)
// because scalar FFMA-3reg is half-rate on sm_103a. Spline via 4-term
// de Boor (degree 3, open uniform knots, 22 internal spans).

#define QDIM   12
#define KDIM   256
#define NCTRL  25
#define BLOCK  256
#define TILE   256
#define KCH    32
#define NCHUNK (KDIM / KCH)      // 8
#define ROWPAD 36
#define BUF_FLOATS (TILE * ROWPAD)               // 9216
#define SMEM_FLOATS (2*BUF_FLOATS + QDIM*KDIM + QDIM*NCTRL + 32)
#define SMEM_BYTES  (SMEM_FLOATS * 4)

__device__ __forceinline__ unsigned long long fma2(unsigned long long a,
                                                   unsigned long long b,
                                                   unsigned long long c) {
    unsigned long long d;
    asm("fma.rn.f32x2 %0, %1, %2, %3;" : "=l"(d) : "l"(a), "l"(b), "l"(c));
    return d;
}

// knots: [0,0,0,0, 1/22 .. 21/22, 1,1,1,1]  -> knot(t) for t in [0,28]
__device__ __forceinline__ float knotv(int t) {
    t -= 3;
    t = t < 0 ? 0 : (t > 22 ? 22 : t);
    return (float)t * (1.0f / 22.0f);
}

__global__ __launch_bounds__(BLOCK, 2)
void kan_bspline_kernel(const float* __restrict__ emb,
                        const float* __restrict__ W,
                        const float* __restrict__ b_inner,
                        const float* __restrict__ inner_scale,
                        const float* __restrict__ coeffs,
                        const float* __restrict__ a_out,
                        const float* __restrict__ b_out,
                        float* __restrict__ out,
                        int npts) {
    extern __shared__ float sh[];
    float* bufs = sh;                          // 2 * BUF_FLOATS
    float* Wsh  = sh + 2 * BUF_FLOATS;         // QDIM*KDIM = 3072
    float* Csh  = Wsh + QDIM * KDIM;           // QDIM*NCTRL = 300
    float* Msh  = Csh + QDIM * NCTRL;          // [0..11]=b_inner [12..23]=a [24]=scale [25]=b_out

    const int tid = threadIdx.x;
    const long long tile0 = (long long)blockIdx.x * TILE;

    // ---- stage constants into smem ----
    for (int i = tid; i < QDIM * KDIM / 4; i += BLOCK)
        ((float4*)Wsh)[i] = ((const float4*)W)[i];
    for (int i = tid; i < QDIM * NCTRL; i += BLOCK)
        Csh[i] = coeffs[i];
    if (tid < QDIM) { Msh[tid] = b_inner[tid]; Msh[12 + tid] = a_out[tid]; }
    if (tid == 0)   { Msh[24] = inner_scale[0]; Msh[25] = b_out[0]; }

    // ---- cp.async chunk loader ----
    const int ccol = tid & 7;     // float4 slot within 32-float chunk row
    const int rb   = tid >> 3;    // base row 0..31

    auto issue = [&](int kc, int b) {
        const float* g0 = emb + (tile0 + rb) * KDIM + kc * KCH + ccol * 4;
        float* s0 = bufs + b * BUF_FLOATS + rb * ROWPAD + ccol * 4;
#pragma unroll
        for (int i = 0; i < TILE / 32; i++) {
            long long prow = tile0 + rb + (long long)i * 32;
            int ok = (prow < (long long)npts);
            const float* gp = ok ? (g0 + (long long)i * 32 * KDIM) : emb;
            int sz = ok ? 16 : 0;
            unsigned sa = (unsigned)__cvta_generic_to_shared(s0 + i * 32 * ROWPAD);
            asm volatile("cp.async.cg.shared.global [%0], [%1], 16, %2;\n"
                         :: "r"(sa), "l"(gp), "r"(sz));
        }
        asm volatile("cp.async.commit_group;\n" ::: "memory");
    };

    unsigned long long acc[QDIM];
#pragma unroll
    for (int q = 0; q < QDIM; q++) acc[q] = 0ULL;   // {0.f, 0.f}

    issue(0, 0);

#pragma unroll 1
    for (int c = 0; c < NCHUNK; c++) {
        if (c + 1 < NCHUNK) {
            issue(c + 1, (c + 1) & 1);
            asm volatile("cp.async.wait_group 1;\n" ::: "memory");
        } else {
            asm volatile("cp.async.wait_group 0;\n" ::: "memory");
        }
        __syncthreads();

        const float* row = bufs + (c & 1) * BUF_FLOATS + tid * ROWPAD;
        const float* wb  = Wsh + c * KCH;
#pragma unroll
        for (int k4 = 0; k4 < KCH / 4; k4++) {
            ulonglong2 x = *(const ulonglong2*)(row + k4 * 4);
#pragma unroll
            for (int q = 0; q < QDIM; q++) {
                ulonglong2 w = *(const ulonglong2*)(wb + q * KDIM + k4 * 4);
                acc[q] = fma2(x.x, w.x, acc[q]);
                acc[q] = fma2(x.y, w.y, acc[q]);
            }
        }
        __syncthreads();
    }

    // ---- epilogue: sigmoid + cubic B-spline (de Boor) per q ----
    long long myp = tile0 + tid;
    if (myp < (long long)npts) {
        const float is = Msh[24];
        float res = Msh[25];
#pragma unroll
        for (int q = 0; q < QDIM; q++) {
            float lo, hi;
            asm("mov.b64 {%0, %1}, %2;" : "=f"(lo), "=f"(hi) : "l"(acc[q]));
            float u = lo + hi + Msh[q];
            // s = 0.5*(tanh(is*u)+1) = 1/(1+exp(-2*is*u))
            float e = __expf(-2.0f * is * u);
            float s = __fdividef(1.0f, 1.0f + e);

            int j = (int)(s * 22.0f);
            j = j < 0 ? 0 : (j > 21 ? 21 : j);
            const int i = j + 3;   // knot span: knots[i] <= s < knots[i+1]

            float Nb[4], lft[4], rgt[4];
            Nb[0] = 1.0f;
#pragma unroll
            for (int p = 1; p <= 3; p++) {
                lft[p] = s - knotv(i + 1 - p);
                rgt[p] = knotv(i + p) - s;
                float saved = 0.0f;
#pragma unroll
                for (int r = 0; r < p; r++) {
                    float den = rgt[r + 1] + lft[p - r];
                    float tmp = __fdividef(Nb[r], den);
                    Nb[r] = fmaf(rgt[r + 1], tmp, saved);
                    saved = lft[p - r] * tmp;
                }
                Nb[p] = saved;
            }
            const float* cq = Csh + q * NCTRL + j;   // coeff index (i-3)..i
            float phi = Nb[0] * cq[0] + Nb[1] * cq[1] + Nb[2] * cq[2] + Nb[3] * cq[3];
            res = fmaf(Msh[12 + q], phi, res);
        }
        out[myp] = res;
    }
}

extern "C" void kernel_launch(void* const* d_in, const int* in_sizes, int n_in,
                              void* d_out, int out_size) {
    const float* emb         = (const float*)d_in[0];
    const float* W           = (const float*)d_in[1];
    const float* b_inner     = (const float*)d_in[2];
    const float* inner_scale = (const float*)d_in[3];
    const float* coeffs      = (const float*)d_in[4];
    const float* a           = (const float*)d_in[5];
    const float* b_out       = (const float*)d_in[6];
    float* out = (float*)d_out;

    int npts = out_size;   // (N_POINTS, 1) float32
    int blocks = (npts + TILE - 1) / TILE;

    cudaFuncSetAttribute(kan_bspline_kernel,
                         cudaFuncAttributeMaxDynamicSharedMemorySize, SMEM_BYTES);
    kan_bspline_kernel<<<blocks, BLOCK, SMEM_BYTES>>>(
        emb, W, b_inner, inner_scale, coeffs, a, b_out, out, npts);
}

// round 2
// speedup vs baseline: 1.2003x; 1.2003x over previous
#include <cuda_runtime.h>
#include <cstdint>

// KA_BSpline_Core: out[n] = b_out + sum_q a[q] * spline_q( sigmoid(2*scale*(emb[n]·W[q]+b_inner[q])) )
//
// R2: 2 points per thread to amortize the W smem-broadcast reads (the R1
// bottleneck: L1/shared 66.7%, ~24 of 40 crossbar phases/pt were W re-reads).
// BLOCK=128, TILE=256 (2 pts/thread), double-buffered cp.async K-chunks of 32.
// GEMV accumulation in packed fma.rn.f32x2 (scalar FFMA is half-rate on sm_103a).

#define QDIM   12
#define KDIM   256
#define NCTRL  25
#define BLOCK  128
#define TILE   256           // points per block (2 per thread)
#define KCH    32
#define NCHUNK (KDIM / KCH)  // 8
#define ROWPAD 36
#define BUF_FLOATS (TILE * ROWPAD)               // 9216
#define SMEM_FLOATS (2*BUF_FLOATS + QDIM*KDIM + QDIM*NCTRL + 32)
#define SMEM_BYTES  (SMEM_FLOATS * 4)

__device__ __forceinline__ unsigned long long fma2(unsigned long long a,
                                                   unsigned long long b,
                                                   unsigned long long c) {
    unsigned long long d;
    asm("fma.rn.f32x2 %0, %1, %2, %3;" : "=l"(d) : "l"(a), "l"(b), "l"(c));
    return d;
}

// knots: [0,0,0,0, 1/22 .. 21/22, 1,1,1,1]  -> knot(t) for t in [0,28]
__device__ __forceinline__ float knotv(int t) {
    t -= 3;
    t = t < 0 ? 0 : (t > 22 ? 22 : t);
    return (float)t * (1.0f / 22.0f);
}

__global__ __launch_bounds__(BLOCK, 2)
void kan_bspline_kernel(const float* __restrict__ emb,
                        const float* __restrict__ W,
                        const float* __restrict__ b_inner,
                        const float* __restrict__ inner_scale,
                        const float* __restrict__ coeffs,
                        const float* __restrict__ a_out,
                        const float* __restrict__ b_out,
                        float* __restrict__ out,
                        int npts) {
    extern __shared__ float sh[];
    float* bufs = sh;                          // 2 * BUF_FLOATS
    float* Wsh  = sh + 2 * BUF_FLOATS;         // QDIM*KDIM = 3072
    float* Csh  = Wsh + QDIM * KDIM;           // QDIM*NCTRL = 300
    float* Msh  = Csh + QDIM * NCTRL;          // [0..11]=b_inner [12..23]=a [24]=scale [25]=b_out

    const int tid = threadIdx.x;
    const long long tile0 = (long long)blockIdx.x * TILE;
    const bool full_tile = (tile0 + TILE) <= (long long)npts;

    // ---- stage constants into smem ----
    for (int i = tid; i < QDIM * KDIM / 4; i += BLOCK)
        ((float4*)Wsh)[i] = ((const float4*)W)[i];
    for (int i = tid; i < QDIM * NCTRL; i += BLOCK)
        Csh[i] = coeffs[i];
    if (tid < QDIM) { Msh[tid] = b_inner[tid]; Msh[12 + tid] = a_out[tid]; }
    if (tid == 0)   { Msh[24] = inner_scale[0]; Msh[25] = b_out[0]; }

    // ---- cp.async chunk loader ----
    // Lanes 0..7 of each 8-lane group write 128B contiguous (row-major):
    // perfectly coalesced on the global side, conflict-free on the smem side.
    const int ccol = tid & 7;     // float4 slot within 32-float chunk row
    const int rb   = tid >> 3;    // base row 0..15

    auto issue = [&](int kc, int b) {
        const float* g0 = emb + (tile0 + rb) * KDIM + kc * KCH + ccol * 4;
        float* s0 = bufs + b * BUF_FLOATS + rb * ROWPAD + ccol * 4;
        if (full_tile) {
#pragma unroll
            for (int i = 0; i < TILE / 16; i++) {
                unsigned sa = (unsigned)__cvta_generic_to_shared(s0 + i * 16 * ROWPAD);
                asm volatile("cp.async.cg.shared.global [%0], [%1], 16;\n"
                             :: "r"(sa), "l"(g0 + (long long)i * 16 * KDIM));
            }
        } else {
#pragma unroll
            for (int i = 0; i < TILE / 16; i++) {
                long long prow = tile0 + rb + (long long)i * 16;
                int ok = (prow < (long long)npts);
                const float* gp = ok ? (g0 + (long long)i * 16 * KDIM) : emb;
                int sz = ok ? 16 : 0;
                unsigned sa = (unsigned)__cvta_generic_to_shared(s0 + i * 16 * ROWPAD);
                asm volatile("cp.async.cg.shared.global [%0], [%1], 16, %2;\n"
                             :: "r"(sa), "l"(gp), "r"(sz));
            }
        }
        asm volatile("cp.async.commit_group;\n" ::: "memory");
    };

    unsigned long long acc0[QDIM], acc1[QDIM];
#pragma unroll
    for (int q = 0; q < QDIM; q++) { acc0[q] = 0ULL; acc1[q] = 0ULL; }

    issue(0, 0);

#pragma unroll 1
    for (int c = 0; c < NCHUNK; c++) {
        if (c + 1 < NCHUNK) {
            issue(c + 1, (c + 1) & 1);
            asm volatile("cp.async.wait_group 1;\n" ::: "memory");
        } else {
            asm volatile("cp.async.wait_group 0;\n" ::: "memory");
        }
        __syncthreads();

        const float* row0 = bufs + (c & 1) * BUF_FLOATS + tid * ROWPAD;
        const float* row1 = row0 + BLOCK * ROWPAD;      // point tid + 128
        const float* wb   = Wsh + c * KCH;
#pragma unroll
        for (int k4 = 0; k4 < KCH / 4; k4++) {
            ulonglong2 x0 = *(const ulonglong2*)(row0 + k4 * 4);
            ulonglong2 x1 = *(const ulonglong2*)(row1 + k4 * 4);
#pragma unroll
            for (int q = 0; q < QDIM; q++) {
                ulonglong2 w = *(const ulonglong2*)(wb + q * KDIM + k4 * 4);
                acc0[q] = fma2(x0.x, w.x, acc0[q]);
                acc0[q] = fma2(x0.y, w.y, acc0[q]);
                acc1[q] = fma2(x1.x, w.x, acc1[q]);
                acc1[q] = fma2(x1.y, w.y, acc1[q]);
            }
        }
        __syncthreads();
    }

    // ---- epilogue: sigmoid + cubic B-spline (de Boor) for both points ----
    const float is = Msh[24];
#pragma unroll
    for (int pp = 0; pp < 2; pp++) {
        long long myp = tile0 + tid + pp * BLOCK;
        if (myp >= (long long)npts) break;
        const unsigned long long* acc = pp ? acc1 : acc0;
        float res = Msh[25];
#pragma unroll
        for (int q = 0; q < QDIM; q++) {
            float lo, hi;
            asm("mov.b64 {%0, %1}, %2;" : "=f"(lo), "=f"(hi) : "l"(acc[q]));
            float u = lo + hi + Msh[q];
            // s = 0.5*(tanh(is*u)+1) = 1/(1+exp(-2*is*u))
            float e = __expf(-2.0f * is * u);
            float s = __fdividef(1.0f, 1.0f + e);

            int j = (int)(s * 22.0f);
            j = j < 0 ? 0 : (j > 21 ? 21 : j);
            const int i = j + 3;   // knot span: knots[i] <= s < knots[i+1]

            float Nb[4], lft[4], rgt[4];
            Nb[0] = 1.0f;
#pragma unroll
            for (int p = 1; p <= 3; p++) {
                lft[p] = s - knotv(i + 1 - p);
                rgt[p] = knotv(i + p) - s;
                float saved = 0.0f;
#pragma unroll
                for (int r = 0; r < p; r++) {
                    float den = rgt[r + 1] + lft[p - r];
                    float tmp = __fdividef(Nb[r], den);
                    Nb[r] = fmaf(rgt[r + 1], tmp, saved);
                    saved = lft[p - r] * tmp;
                }
                Nb[p] = saved;
            }
            const float* cq = Csh + q * NCTRL + j;   // coeff index (i-3)..i
            float phi = Nb[0] * cq[0] + Nb[1] * cq[1] + Nb[2] * cq[2] + Nb[3] * cq[3];
            res = fmaf(Msh[12 + q], phi, res);
        }
        out[myp] = res;
    }
}

extern "C" void kernel_launch(void* const* d_in, const int* in_sizes, int n_in,
                              void* d_out, int out_size) {
    const float* emb         = (const float*)d_in[0];
    const float* W           = (const float*)d_in[1];
    const float* b_inner     = (const float*)d_in[2];
    const float* inner_scale = (const float*)d_in[3];
    const float* coeffs      = (const float*)d_in[4];
    const float* a           = (const float*)d_in[5];
    const float* b_out       = (const float*)d_in[6];
    float* out = (float*)d_out;

    int npts = out_size;   // (N_POINTS, 1) float32
    int blocks = (npts + TILE - 1) / TILE;

    cudaFuncSetAttribute(kan_bspline_kernel,
                         cudaFuncAttributeMaxDynamicSharedMemorySize, SMEM_BYTES);
    kan_bspline_kernel<<<blocks, BLOCK, SMEM_BYTES>>>(
        emb, W, b_inner, inner_scale, coeffs, a, b_out, out, npts);
}

// round 3
// speedup vs baseline: 1.3443x; 1.1200x over previous
#include <cuda_runtime.h>
#include <cstdint>

// KA_BSpline_Core: out[n] = b_out + sum_q a[q] * spline_q( sigmoid(2*scale*(emb[n]·W[q]+b_inner[q])) )
//
// R3: overlap was the binding constraint (occ 12%, DRAM 53%, nothing >55%).
// Shrink smem/CTA 87KB -> 45.5KB via XOR-swizzled unpadded buffers (KCH=16)
// so 4 CTAs/SM (16 warps) run at staggered pipeline phases.

#define QDIM   12
#define KDIM   256
#define NCTRL  25
#define BLOCK  128
#define TILE   256           // points per block (2 per thread)
#define KCH    16
#define NCHUNK (KDIM / KCH)  // 16
#define BUF_FLOATS (TILE * KCH)                  // 4096
#define SMEM_FLOATS (2*BUF_FLOATS + QDIM*KDIM + QDIM*NCTRL + 32)
#define SMEM_BYTES  (SMEM_FLOATS * 4)

__device__ __forceinline__ unsigned long long fma2(unsigned long long a,
                                                   unsigned long long b,
                                                   unsigned long long c) {
    unsigned long long d;
    asm("fma.rn.f32x2 %0, %1, %2, %3;" : "=l"(d) : "l"(a), "l"(b), "l"(c));
    return d;
}

// knots: [0,0,0,0, 1/22 .. 21/22, 1,1,1,1]  -> knot(t) for t in [0,28]
__device__ __forceinline__ float knotv(int t) {
    t -= 3;
    t = t < 0 ? 0 : (t > 22 ? 22 : t);
    return (float)t * (1.0f / 22.0f);
}

__global__ __launch_bounds__(BLOCK, 4)
void kan_bspline_kernel(const float* __restrict__ emb,
                        const float* __restrict__ W,
                        const float* __restrict__ b_inner,
                        const float* __restrict__ inner_scale,
                        const float* __restrict__ coeffs,
                        const float* __restrict__ a_out,
                        const float* __restrict__ b_out,
                        float* __restrict__ out,
                        int npts) {
    extern __shared__ float sh[];
    float* bufs = sh;                          // 2 * BUF_FLOATS
    float* Wsh  = sh + 2 * BUF_FLOATS;         // QDIM*KDIM = 3072
    float* Csh  = Wsh + QDIM * KDIM;           // QDIM*NCTRL = 300
    float* Msh  = Csh + QDIM * NCTRL;          // [0..11]=b_inner [12..23]=a [24]=scale [25]=b_out

    const int tid = threadIdx.x;
    const long long tile0 = (long long)blockIdx.x * TILE;
    const bool full_tile = (tile0 + TILE) <= (long long)npts;

    // ---- stage constants into smem ----
    for (int i = tid; i < QDIM * KDIM / 4; i += BLOCK)
        ((float4*)Wsh)[i] = ((const float4*)W)[i];
    for (int i = tid; i < QDIM * NCTRL; i += BLOCK)
        Csh[i] = coeffs[i];
    if (tid < QDIM) { Msh[tid] = b_inner[tid]; Msh[12 + tid] = a_out[tid]; }
    if (tid == 0)   { Msh[24] = inner_scale[0]; Msh[25] = b_out[0]; }

    // ---- cp.async chunk loader (XOR-swizzled, unpadded rows of 16 floats) ----
    // smem slot for (row, k4-group): slot = k4 ^ ((row>>1)&3)
    //  fill phase: 2 rows x 4 lanes cover disjoint 64B halves of 128B -> conflict-free
    //  read phase: 8 rows hit all 8 distinct 16B positions mod 128B -> conflict-free
    const int ccol = tid & 3;     // float4 slot within 16-float chunk row (global order)
    const int rb   = tid >> 2;    // base row 0..31

    auto issue = [&](int kc, int b) {
        const float* g0 = emb + (tile0 + rb) * KDIM + kc * KCH + ccol * 4;
        if (full_tile) {
#pragma unroll
            for (int i = 0; i < TILE / 32; i++) {
                int row = rb + i * 32;
                int slot = ccol ^ ((row >> 1) & 3);
                float* s0 = bufs + b * BUF_FLOATS + row * KCH + slot * 4;
                unsigned sa = (unsigned)__cvta_generic_to_shared(s0);
                asm volatile("cp.async.cg.shared.global [%0], [%1], 16;\n"
                             :: "r"(sa), "l"(g0 + (long long)i * 32 * KDIM));
            }
        } else {
#pragma unroll
            for (int i = 0; i < TILE / 32; i++) {
                int row = rb + i * 32;
                long long prow = tile0 + row;
                int ok = (prow < (long long)npts);
                const float* gp = ok ? (g0 + (long long)i * 32 * KDIM) : emb;
                int sz = ok ? 16 : 0;
                int slot = ccol ^ ((row >> 1) & 3);
                float* s0 = bufs + b * BUF_FLOATS + row * KCH + slot * 4;
                unsigned sa = (unsigned)__cvta_generic_to_shared(s0);
                asm volatile("cp.async.cg.shared.global [%0], [%1], 16, %2;\n"
                             :: "r"(sa), "l"(gp), "r"(sz));
            }
        }
        asm volatile("cp.async.commit_group;\n" ::: "memory");
    };

    unsigned long long acc0[QDIM], acc1[QDIM];
#pragma unroll
    for (int q = 0; q < QDIM; q++) { acc0[q] = 0ULL; acc1[q] = 0ULL; }

    issue(0, 0);

    const int sw = (tid >> 1) & 3;   // same swizzle for row tid and tid+128

#pragma unroll 1
    for (int c = 0; c < NCHUNK; c++) {
        if (c + 1 < NCHUNK) {
            issue(c + 1, (c + 1) & 1);
            asm volatile("cp.async.wait_group 1;\n" ::: "memory");
        } else {
            asm volatile("cp.async.wait_group 0;\n" ::: "memory");
        }
        __syncthreads();

        const float* row0 = bufs + (c & 1) * BUF_FLOATS + tid * KCH;
        const float* row1 = row0 + BLOCK * KCH;         // point tid + 128
        const float* wb   = Wsh + c * KCH;
#pragma unroll
        for (int k4 = 0; k4 < KCH / 4; k4++) {
            const int slot = (k4 ^ sw) * 4;
            ulonglong2 x0 = *(const ulonglong2*)(row0 + slot);
            ulonglong2 x1 = *(const ulonglong2*)(row1 + slot);
#pragma unroll
            for (int q = 0; q < QDIM; q++) {
                ulonglong2 w = *(const ulonglong2*)(wb + q * KDIM + k4 * 4);
                acc0[q] = fma2(x0.x, w.x, acc0[q]);
                acc0[q] = fma2(x0.y, w.y, acc0[q]);
                acc1[q] = fma2(x1.x, w.x, acc1[q]);
                acc1[q] = fma2(x1.y, w.y, acc1[q]);
            }
        }
        __syncthreads();
    }

    // ---- epilogue: sigmoid + cubic B-spline (de Boor) for both points ----
    const float is = Msh[24];
#pragma unroll
    for (int pp = 0; pp < 2; pp++) {
        long long myp = tile0 + tid + pp * BLOCK;
        if (myp >= (long long)npts) break;
        const unsigned long long* acc = pp ? acc1 : acc0;
        float res = Msh[25];
#pragma unroll
        for (int q = 0; q < QDIM; q++) {
            float lo, hi;
            asm("mov.b64 {%0, %1}, %2;" : "=f"(lo), "=f"(hi) : "l"(acc[q]));
            float u = lo + hi + Msh[q];
            // s = 0.5*(tanh(is*u)+1) = 1/(1+exp(-2*is*u))
            float e = __expf(-2.0f * is * u);
            float s = __fdividef(1.0f, 1.0f + e);

            int j = (int)(s * 22.0f);
            j = j < 0 ? 0 : (j > 21 ? 21 : j);
            const int i = j + 3;   // knot span: knots[i] <= s < knots[i+1]

            float Nb[4], lft[4], rgt[4];
            Nb[0] = 1.0f;
#pragma unroll
            for (int p = 1; p <= 3; p++) {
                lft[p] = s - knotv(i + 1 - p);
                rgt[p] = knotv(i + p) - s;
                float saved = 0.0f;
#pragma unroll
                for (int r = 0; r < p; r++) {
                    float den = rgt[r + 1] + lft[p - r];
                    float tmp = __fdividef(Nb[r], den);
                    Nb[r] = fmaf(rgt[r + 1], tmp, saved);
                    saved = lft[p - r] * tmp;
                }
                Nb[p] = saved;
            }
            const float* cq = Csh + q * NCTRL + j;   // coeff index (i-3)..i
            float phi = Nb[0] * cq[0] + Nb[1] * cq[1] + Nb[2] * cq[2] + Nb[3] * cq[3];
            res = fmaf(Msh[12 + q], phi, res);
        }
        out[myp] = res;
    }
}

extern "C" void kernel_launch(void* const* d_in, const int* in_sizes, int n_in,
                              void* d_out, int out_size) {
    const float* emb         = (const float*)d_in[0];
    const float* W           = (const float*)d_in[1];
    const float* b_inner     = (const float*)d_in[2];
    const float* inner_scale = (const float*)d_in[3];
    const float* coeffs      = (const float*)d_in[4];
    const float* a           = (const float*)d_in[5];
    const float* b_out       = (const float*)d_in[6];
    float* out = (float*)d_out;

    int npts = out_size;   // (N_POINTS, 1) float32
    int blocks = (npts + TILE - 1) / TILE;

    cudaFuncSetAttribute(kan_bspline_kernel,
                         cudaFuncAttributeMaxDynamicSharedMemorySize, SMEM_BYTES);
    kan_bspline_kernel<<<blocks, BLOCK, SMEM_BYTES>>>(
        emb, W, b_inner, inner_scale, coeffs, a, b_out, out, npts);
}

// round 5
// speedup vs baseline: 1.3932x; 1.0364x over previous
#include <cuda_runtime.h>
#include <cstdint>

// KA_BSpline_Core: out[n] = b_out + sum_q a[q] * spline_q( sigmoid(2*scale*(emb[n]·W[q]+b_inner[q])) )
//
// R4: warp-synchronous pipeline. Each warp cp.asyncs exactly the 64 rows its
// own lanes consume (rows w*32..w*32+31 and +128), so the per-chunk handshake
// is wait_group + __syncwarp only -- ZERO block barriers in the mainloop.
// 16 fully independent warp pipelines per SM at staggered phases.

#define QDIM   12
#define KDIM   256
#define NCTRL  25
#define BLOCK  128
#define TILE   256           // points per block (2 per thread)
#define KCH    16
#define NCHUNK (KDIM / KCH)  // 16
#define BUF_FLOATS (TILE * KCH)                  // 4096
#define SMEM_FLOATS (2*BUF_FLOATS + QDIM*KDIM + QDIM*NCTRL + 32)
#define SMEM_BYTES  (SMEM_FLOATS * 4)

__device__ __forceinline__ unsigned long long fma2(unsigned long long a,
                                                   unsigned long long b,
                                                   unsigned long long c) {
    unsigned long long d;
    asm("fma.rn.f32x2 %0, %1, %2, %3;" : "=l"(d) : "l"(a), "l"(b), "l"(c));
    return d;
}

// knots: [0,0,0,0, 1/22 .. 21/22, 1,1,1,1]  -> knot(t) for t in [0,28]
__device__ __forceinline__ float knotv(int t) {
    t -= 3;
    t = t < 0 ? 0 : (t > 22 ? 22 : t);
    return (float)t * (1.0f / 22.0f);
}

__global__ __launch_bounds__(BLOCK, 4)
void kan_bspline_kernel(const float* __restrict__ emb,
                        const float* __restrict__ W,
                        const float* __restrict__ b_inner,
                        const float* __restrict__ inner_scale,
                        const float* __restrict__ coeffs,
                        const float* __restrict__ a_out,
                        const float* __restrict__ b_out,
                        float* __restrict__ out,
                        int npts) {
    extern __shared__ float sh[];
    float* bufs = sh;                          // 2 * BUF_FLOATS
    float* Wsh  = sh + 2 * BUF_FLOATS;         // QDIM*KDIM = 3072
    float* Csh  = Wsh + QDIM * KDIM;           // QDIM*NCTRL = 300
    float* Msh  = Csh + QDIM * NCTRL;          // [0..11]=b_inner [12..23]=a [24]=scale [25]=b_out

    const int tid  = threadIdx.x;
    const int wid  = tid >> 5;                 // warp 0..3
    const int lane = tid & 31;
    const long long tile0 = (long long)blockIdx.x * TILE;
    const bool full_tile = (tile0 + TILE) <= (long long)npts;

    // ---- stage constants into smem ----
    for (int i = tid; i < QDIM * KDIM / 4; i += BLOCK)
        ((float4*)Wsh)[i] = ((const float4*)W)[i];
    for (int i = tid; i < QDIM * NCTRL; i += BLOCK)
        Csh[i] = coeffs[i];
    if (tid < QDIM) { Msh[tid] = b_inner[tid]; Msh[12 + tid] = a_out[tid]; }
    if (tid == 0)   { Msh[24] = inner_scale[0]; Msh[25] = b_out[0]; }
    __syncthreads();   // the only block barrier

    // ---- warp-private cp.async loader ----
    // Warp w loads exactly the rows its own lanes consume:
    //   rows w*32 .. w*32+31   (point tid,     acc0)
    //   rows 128+w*32 .. +31   (point tid+128, acc1)
    // Lane l covers float4-slot (l&3) of rows (w*32 + (l>>2) + 8i), i=0..3, both halves.
    // XOR swizzle: slot = ccol ^ ((row>>1)&3) -> conflict-free fill & read.
    const int ccol  = lane & 3;
    const int rsub  = lane >> 2;               // 0..7
    const int rbase = wid * 32 + rsub;

    auto issue = [&](int kc, int b) {
        float* bb = bufs + b * BUF_FLOATS;
        const float* g0 = emb + kc * KCH + ccol * 4;
        if (full_tile) {
#pragma unroll
            for (int h = 0; h < 2; h++) {
#pragma unroll
                for (int i = 0; i < 4; i++) {
                    int row = h * 128 + rbase + 8 * i;
                    int slot = ccol ^ ((row >> 1) & 3);
                    unsigned sa = (unsigned)__cvta_generic_to_shared(bb + row * KCH + slot * 4);
                    asm volatile("cp.async.cg.shared.global [%0], [%1], 16;\n"
                                 :: "r"(sa), "l"(g0 + (tile0 + row) * KDIM));
                }
            }
        } else {
#pragma unroll
            for (int h = 0; h < 2; h++) {
#pragma unroll
                for (int i = 0; i < 4; i++) {
                    int row = h * 128 + rbase + 8 * i;
                    long long prow = tile0 + row;
                    int ok = (prow < (long long)npts);
                    const float* gp = ok ? (g0 + prow * KDIM) : emb;
                    int sz = ok ? 16 : 0;
                    int slot = ccol ^ ((row >> 1) & 3);
                    unsigned sa = (unsigned)__cvta_generic_to_shared(bb + row * KCH + slot * 4);
                    asm volatile("cp.async.cg.shared.global [%0], [%1], 16, %2;\n"
                                 :: "r"(sa), "l"(gp), "r"(sz));
                }
            }
        }
        asm volatile("cp.async.commit_group;\n" ::: "memory");
    };

    unsigned long long acc0[QDIM], acc1[QDIM];
#pragma unroll
    for (int q = 0; q < QDIM; q++) { acc0[q] = 0ULL; acc1[q] = 0ULL; }

    issue(0, 0);

    const int sw = (tid >> 1) & 3;   // read-side swizzle (same for row tid and tid+128)

#pragma unroll 1
    for (int c = 0; c < NCHUNK; c++) {
        if (c + 1 < NCHUNK) {
            issue(c + 1, (c + 1) & 1);
            asm volatile("cp.async.wait_group 1;\n" ::: "memory");
        } else {
            asm volatile("cp.async.wait_group 0;\n" ::: "memory");
        }
        __syncwarp();

        const float* row0 = bufs + (c & 1) * BUF_FLOATS + tid * KCH;
        const float* row1 = row0 + BLOCK * KCH;         // point tid + 128
        const float* wb   = Wsh + c * KCH;
#pragma unroll
        for (int k4 = 0; k4 < KCH / 4; k4++) {
            const int slot = (k4 ^ sw) * 4;
            ulonglong2 x0 = *(const ulonglong2*)(row0 + slot);
            ulonglong2 x1 = *(const ulonglong2*)(row1 + slot);
#pragma unroll
            for (int q = 0; q < QDIM; q++) {
                ulonglong2 w = *(const ulonglong2*)(wb + q * KDIM + k4 * 4);
                acc0[q] = fma2(x0.x, w.x, acc0[q]);
                acc0[q] = fma2(x0.y, w.y, acc0[q]);
                acc1[q] = fma2(x1.x, w.x, acc1[q]);
                acc1[q] = fma2(x1.y, w.y, acc1[q]);
            }
        }
        __syncwarp();
    }

    // ---- epilogue: sigmoid + cubic B-spline (de Boor) for both points ----
    const float is = Msh[24];
#pragma unroll
    for (int pp = 0; pp < 2; pp++) {
        long long myp = tile0 + tid + pp * BLOCK;
        if (myp >= (long long)npts) break;
        const unsigned long long* acc = pp ? acc1 : acc0;
        float res = Msh[25];
#pragma unroll
        for (int q = 0; q < QDIM; q++) {
            float lo, hi;
            asm("mov.b64 {%0, %1}, %2;" : "=f"(lo), "=f"(hi) : "l"(acc[q]));
            float u = lo + hi + Msh[q];
            // s = 0.5*(tanh(is*u)+1) = 1/(1+exp(-2*is*u))
            float e = __expf(-2.0f * is * u);
            float s = __fdividef(1.0f, 1.0f + e);

            int j = (int)(s * 22.0f);
            j = j < 0 ? 0 : (j > 21 ? 21 : j);
            const int i = j + 3;   // knot span: knots[i] <= s < knots[i+1]

            float Nb[4], lft[4], rgt[4];
            Nb[0] = 1.0f;
#pragma unroll
            for (int p = 1; p <= 3; p++) {
                lft[p] = s - knotv(i + 1 - p);
                rgt[p] = knotv(i + p) - s;
                float saved = 0.0f;
#pragma unroll
                for (int r = 0; r < p; r++) {
                    float den = rgt[r + 1] + lft[p - r];
                    float tmp = __fdividef(Nb[r], den);
                    Nb[r] = fmaf(rgt[r + 1], tmp, saved);
                    saved = lft[p - r] * tmp;
                }
                Nb[p] = saved;
            }
            const float* cq = Csh + q * NCTRL + j;   // coeff index (i-3)..i
            float phi = Nb[0] * cq[0] + Nb[1] * cq[1] + Nb[2] * cq[2] + Nb[3] * cq[3];
            res = fmaf(Msh[12 + q], phi, res);
        }
        out[myp] = res;
    }
}

extern "C" void kernel_launch(void* const* d_in, const int* in_sizes, int n_in,
                              void* d_out, int out_size) {
    const float* emb         = (const float*)d_in[0];
    const float* W           = (const float*)d_in[1];
    const float* b_inner     = (const float*)d_in[2];
    const float* inner_scale = (const float*)d_in[3];
    const float* coeffs      = (const float*)d_in[4];
    const float* a           = (const float*)d_in[5];
    const float* b_out       = (const float*)d_in[6];
    float* out = (float*)d_out;

    int npts = out_size;   // (N_POINTS, 1) float32
    int blocks = (npts + TILE - 1) / TILE;

    cudaFuncSetAttribute(kan_bspline_kernel,
                         cudaFuncAttributeMaxDynamicSharedMemorySize, SMEM_BYTES);
    kan_bspline_kernel<<<blocks, BLOCK, SMEM_BYTES>>>(
        emb, W, b_inner, inner_scale, coeffs, a, b_out, out, npts);
}